// round 2
// baseline (speedup 1.0000x reference)
#include <cuda_runtime.h>
#include <cuda_bf16.h>
#include <cstdint>

// Problem shape (fixed for this problem instance)
#define NVARS  100000
#define NFACT  50000
#define NEDGES 1000000
#define DIM    128

// Scratch (no cudaMalloc allowed) — device globals
__device__ float g_P[(size_t)NVARS * DIM];     // variables @ W1
__device__ float g_Q[(size_t)NFACT * DIM];     // factors  @ W2
__device__ float g_aggr[(size_t)NVARS * DIM];  // segment_sum of messages

// ---------------------------------------------------------------------------
// Generic tiled GEMM: C[M,128] = sum_h A_h[M,128] @ W[h*128 : h*128+128, 0:128]
// Optional epilogue: C = resid + relu(acc + bias)
// Block: 256 threads, 64 rows per block. Each warp owns 8 rows; each thread
// computes 8 rows x 4 cols (cols = lane*4..lane*4+3).
// Dynamic smem: sW[128][128] + sA[64][128]  = 96 KB.
// ---------------------------------------------------------------------------
__global__ __launch_bounds__(256) void gemm128_kernel(
    const float* __restrict__ A0, const float* __restrict__ A1,
    const float* __restrict__ W, int nhalves,
    const float* __restrict__ bias, const float* __restrict__ resid,
    float* __restrict__ C, int M)
{
    extern __shared__ float smem[];
    float* sW = smem;              // 128*128 floats
    float* sA = smem + 128 * 128;  // 64*128 floats

    const int tid  = threadIdx.x;
    const int lane = tid & 31;
    const int warp = tid >> 5;
    const int row0 = blockIdx.x * 64;
    const int rows = (M - row0 < 64) ? (M - row0) : 64;

    float acc[8][4];
#pragma unroll
    for (int r = 0; r < 8; r++) {
        acc[r][0] = 0.f; acc[r][1] = 0.f; acc[r][2] = 0.f; acc[r][3] = 0.f;
    }

    for (int h = 0; h < nhalves; h++) {
        const float* Wh = W + (size_t)h * 128 * 128;
        const float* Ah = (h == 0) ? A0 : A1;
        __syncthreads();
        // Stage W half: 16384 floats as float4, coalesced linear copy
#pragma unroll 4
        for (int i = tid; i < (128 * 128) / 4; i += 256)
            reinterpret_cast<float4*>(sW)[i] =
                reinterpret_cast<const float4*>(Wh)[i];
        // Stage A tile: rows*128 floats
        const float4* Asrc = reinterpret_cast<const float4*>(Ah + (size_t)row0 * 128);
        for (int i = tid; i < rows * 32; i += 256)
            reinterpret_cast<float4*>(sA)[i] = Asrc[i];
        __syncthreads();

        const int myrow = warp * 8;
#pragma unroll 4
        for (int k = 0; k < 128; k++) {
            float4 w = reinterpret_cast<const float4*>(sW + k * 128)[lane];
#pragma unroll
            for (int r = 0; r < 8; r++) {
                float a = sA[(myrow + r) * 128 + k];
                acc[r][0] = fmaf(a, w.x, acc[r][0]);
                acc[r][1] = fmaf(a, w.y, acc[r][1]);
                acc[r][2] = fmaf(a, w.z, acc[r][2]);
                acc[r][3] = fmaf(a, w.w, acc[r][3]);
            }
        }
    }

    // Epilogue
    const int col = lane * 4;
    float4 b4 = make_float4(0.f, 0.f, 0.f, 0.f);
    if (bias) b4 = *reinterpret_cast<const float4*>(bias + col);
#pragma unroll
    for (int r = 0; r < 8; r++) {
        int row = row0 + warp * 8 + r;
        if (row < M) {
            float4 v;
            v.x = acc[r][0]; v.y = acc[r][1]; v.z = acc[r][2]; v.w = acc[r][3];
            if (bias) {
                v.x = fmaxf(v.x + b4.x, 0.f);
                v.y = fmaxf(v.y + b4.y, 0.f);
                v.z = fmaxf(v.z + b4.z, 0.f);
                v.w = fmaxf(v.w + b4.w, 0.f);
            }
            if (resid) {
                float4 rv = *reinterpret_cast<const float4*>(resid + (size_t)row * 128 + col);
                v.x += rv.x; v.y += rv.y; v.z += rv.z; v.w += rv.w;
            }
            *reinterpret_cast<float4*>(C + (size_t)row * 128 + col) = v;
        }
    }
}

// ---------------------------------------------------------------------------
// Edge kernel: one warp per edge.
//   m = relu(P[v] + Q[f] + b_msg);  aggr[v] += m  (vectorized L2 reduction)
// ---------------------------------------------------------------------------
__global__ __launch_bounds__(256) void edge_kernel(
    const int* __restrict__ v_to_f, const int* __restrict__ f_to_v,
    const float* __restrict__ bmsg, int E)
{
    const int gwarp = (blockIdx.x * blockDim.x + threadIdx.x) >> 5;
    if (gwarp >= E) return;
    const int lane = threadIdx.x & 31;
    const int v = __ldg(v_to_f + gwarp);
    const int f = __ldg(f_to_v + gwarp);
    const int c = lane * 4;

    float4 p = *reinterpret_cast<const float4*>(g_P + (size_t)v * 128 + c);
    float4 q = *reinterpret_cast<const float4*>(g_Q + (size_t)f * 128 + c);
    float4 b = __ldg(reinterpret_cast<const float4*>(bmsg + c));

    float m0 = fmaxf(p.x + q.x + b.x, 0.f);
    float m1 = fmaxf(p.y + q.y + b.y, 0.f);
    float m2 = fmaxf(p.z + q.z + b.z, 0.f);
    float m3 = fmaxf(p.w + q.w + b.w, 0.f);

    float* dst = g_aggr + (size_t)v * 128 + c;
    asm volatile("red.global.add.v4.f32 [%0], {%1, %2, %3, %4};"
                 :: "l"(dst), "f"(m0), "f"(m1), "f"(m2), "f"(m3)
                 : "memory");
}

// ---------------------------------------------------------------------------
// Launch
// ---------------------------------------------------------------------------
extern "C" void kernel_launch(void* const* d_in, const int* in_sizes, int n_in,
                              void* d_out, int out_size)
{
    const float* variables = (const float*)d_in[0];
    const float* factors   = (const float*)d_in[1];
    const int*   v_to_f    = (const int*)d_in[2];
    const int*   f_to_v    = (const int*)d_in[3];
    // d_in[4] = edge_attr: unused (reference zeroes it)
    const float* W_msg     = (const float*)d_in[5];  // [257,128]
    const float* b_msg     = (const float*)d_in[6];  // [128]
    const float* W_comb    = (const float*)d_in[7];  // [256,128]
    const float* b_comb    = (const float*)d_in[8];  // [128]
    float* out = (float*)d_out;

    const int n_vars = in_sizes[0] / DIM;
    const int n_fact = in_sizes[1] / DIM;
    const int n_edge = in_sizes[2];

    float *pP = nullptr, *pQ = nullptr, *pAggr = nullptr;
    cudaGetSymbolAddress((void**)&pP, g_P);
    cudaGetSymbolAddress((void**)&pQ, g_Q);
    cudaGetSymbolAddress((void**)&pAggr, g_aggr);

    const size_t smem_bytes = (128 * 128 + 64 * 128) * sizeof(float);  // 96 KB
    cudaFuncSetAttribute(gemm128_kernel,
                         cudaFuncAttributeMaxDynamicSharedMemorySize,
                         (int)smem_bytes);

    cudaStream_t s = 0;

    // 1) zero aggregation buffer
    cudaMemsetAsync(pAggr, 0, (size_t)n_vars * DIM * sizeof(float), s);

    // 2) P = variables @ W_msg[0:128]     (no bias/relu yet)
    gemm128_kernel<<<(n_vars + 63) / 64, 256, smem_bytes, s>>>(
        variables, nullptr, W_msg, 1, nullptr, nullptr, pP, n_vars);

    // 3) Q = factors @ W_msg[128:256]
    gemm128_kernel<<<(n_fact + 63) / 64, 256, smem_bytes, s>>>(
        factors, nullptr, W_msg + 128 * 128, 1, nullptr, nullptr, pQ, n_fact);

    // 4) per-edge relu + scatter-add
    int edge_blocks = (n_edge + 7) / 8;  // 8 warps (edges) per 256-thread block
    edge_kernel<<<edge_blocks, 256, 0, s>>>(v_to_f, f_to_v, b_msg, n_edge);

    // 5) out = variables + relu(variables@Wc1 + aggr@Wc2 + b_comb)
    gemm128_kernel<<<(n_vars + 63) / 64, 256, smem_bytes, s>>>(
        variables, pAggr, W_comb, 2, b_comb, variables, out, n_vars);
}